// round 4
// baseline (speedup 1.0000x reference)
#include <cuda_runtime.h>
#include <math.h>

// Problem constants (fixed shapes: z = (16, 128, 64, 64) fp32, codebook = (1024, 128) fp32)
#define CDIM    128
#define KCODES  1024
#define HWDIM   4096          // 64*64 pixels per batch image
#define NPIXMAX 65536         // 16 * 4096
#define PBLOCKS 1024          // quant partial blocks

// ---- scratch (no allocations allowed; __device__ globals are the sanctioned path) ----
__device__ float  g_ee[KCODES];          // per-code sum(e^2), sequential fp32
__device__ int    g_idx[NPIXMAX];        // argmin indices
__device__ int    g_counts[KCODES];      // code histogram
__device__ double g_partials[PBLOCKS];   // deterministic per-block loss partials
__device__ float  g_idx_scratch[NPIXMAX];// fallback index sink if out buffer too small

// ---- packed fp32x2 helpers (lanewise IEEE fp32 => numerics identical to scalar) ----
__device__ __forceinline__ unsigned long long dup_f32(float x) {
    unsigned long long r;
    asm("mov.b64 %0, {%1, %1};" : "=l"(r) : "f"(x));
    return r;
}
__device__ __forceinline__ void fma_f32x2(unsigned long long& d,
                                          unsigned long long a,
                                          unsigned long long b) {
    asm("fma.rn.f32x2 %0, %1, %2, %3;" : "=l"(d) : "l"(a), "l"(b), "l"(d));
}
__device__ __forceinline__ void unpack_f32x2(float& lo, float& hi, unsigned long long v) {
    asm("mov.b64 {%0, %1}, %2;" : "=f"(lo), "=f"(hi) : "l"(v));
}

// ------------------------------------------------------------------
__global__ void zero_counts_kernel() {
    int i = blockIdx.x * blockDim.x + threadIdx.x;
    if (i < KCODES) g_counts[i] = 0;
}

// ------------------------------------------------------------------
__global__ void ee_kernel(const float* __restrict__ cb) {
    int k = blockIdx.x * blockDim.x + threadIdx.x;
    if (k >= KCODES) return;
    const float* p = cb + (size_t)k * CDIM;
    float s = 0.0f;
#pragma unroll
    for (int c = 0; c < CDIM; c++) {
        float v = p[c];
        s = __fadd_rn(s, __fmul_rn(v, v));
    }
    g_ee[k] = s;
}

// ------------------------------------------------------------------
// argmin: block = 64 pixels x all 1024 codes, 256 threads.
// z tile (64px x 128c = 32KB) loaded to smem ONCE; codebook streamed
// as double-buffered (128 codes x 16 c) chunks with prefetch -> one
// barrier per chunk, global latency hidden. Inner product uses packed
// fma.rn.f32x2 over pixel pairs; per-lane chain = sequential ascending
// c (identical rounding to scalar reference path, validated R1/R2).
// d2 = fl(fl(zz - fl(2*dot)) + ee); first-minimum tie-break.
// ------------------------------------------------------------------
__global__ void __launch_bounds__(256, 2) argmin_kernel(
        const float* __restrict__ z, const float* __restrict__ cb) {
    __shared__ __align__(16) float zs[CDIM][64];      // c-major: pixel pairs adjacent
    __shared__ __align__(16) float es[2][16][132];    // [buf][ci][code], pad vs conflicts

    const int tid  = threadIdx.x;
    const int lane = tid & 31;
    const int tp   = tid >> 5;

    const int n0  = blockIdx.x * 64;        // 4096 % 64 == 0 -> tile never straddles b
    const int b   = n0 >> 12;
    const int hw0 = n0 & (HWDIM - 1);
    const float* zbase = z + ((size_t)b * CDIM) * HWDIM + hw0;

    // ---- load full z tile (128 rows x 64 floats, float4, coalesced) ----
#pragma unroll
    for (int pass = 0; pass < 8; pass++) {
        int r = (tid >> 4) + pass * 16;
        int q = (tid & 15) * 4;
        *(float4*)&zs[r][q] = *(const float4*)(zbase + (size_t)r * HWDIM + q);
    }
    // ---- prefetch codebook chunk 0 (kt=0, c 0..15) ----
    {
        int kk = tid & 127;
        int hb = (tid >> 7) * 8;
        const float* src = cb + (size_t)kk * CDIM + hb;
#pragma unroll
        for (int i = 0; i < 2; i++) {
            float4 v = *(const float4*)(src + i * 4);
            es[0][hb + i * 4 + 0][kk] = v.x;
            es[0][hb + i * 4 + 1][kk] = v.y;
            es[0][hb + i * 4 + 2][kk] = v.z;
            es[0][hb + i * 4 + 3][kk] = v.w;
        }
    }
    __syncthreads();

    // ---- zz from smem: strictly sequential fp32 (matches reference reduce) ----
    float zzr[8];
#pragma unroll
    for (int pp = 0; pp < 8; pp++) zzr[pp] = 0.0f;
    for (int c = 0; c < CDIM; c++) {
#pragma unroll
        for (int pp = 0; pp < 8; pp++) {
            float v = zs[c][tp * 8 + pp];
            zzr[pp] = __fadd_rn(zzr[pp], __fmul_rn(v, v));
        }
    }

    float bestv[8];
    int   besti[8];
#pragma unroll
    for (int pp = 0; pp < 8; pp++) { bestv[pp] = 3.4e38f; besti[pp] = 0x7fffffff; }

#pragma unroll 1
    for (int kt = 0; kt < 8; kt++) {
        // acc[pq][j]: pq = pixel pair (lo = pixel 2pq, hi = 2pq+1), j = code
        unsigned long long acc[4][4];
#pragma unroll
        for (int pq = 0; pq < 4; pq++)
#pragma unroll
            for (int j = 0; j < 4; j++) acc[pq][j] = 0ull;

#pragma unroll 1
        for (int cc = 0; cc < 8; cc++) {
            const int g   = kt * 8 + cc;
            const int buf = g & 1;
            // prefetch next chunk into the other buffer (overlaps compute)
            if (g + 1 < 64) {
                int nk  = (g + 1) >> 3;
                int ncc = (g + 1) & 7;
                int nb  = (g + 1) & 1;
                int kk  = tid & 127;
                int hb  = (tid >> 7) * 8;
                const float* src =
                    cb + (size_t)(nk * 128 + kk) * CDIM + ncc * 16 + hb;
#pragma unroll
                for (int i = 0; i < 2; i++) {
                    float4 v = *(const float4*)(src + i * 4);
                    es[nb][hb + i * 4 + 0][kk] = v.x;
                    es[nb][hb + i * 4 + 1][kk] = v.y;
                    es[nb][hb + i * 4 + 2][kk] = v.z;
                    es[nb][hb + i * 4 + 3][kk] = v.w;
                }
            }
            // compute 16 c-slices of this chunk
#pragma unroll
            for (int t = 0; t < 16; t++) {
                const int c = cc * 16 + t;
                // pixel pairs via 128-bit broadcast loads (2 wavefronts total)
                ulonglong2 zlo = *(const ulonglong2*)&zs[c][tp * 8];
                ulonglong2 zhi = *(const ulonglong2*)&zs[c][tp * 8 + 4];
                float4 er = *(const float4*)&es[buf][t][lane * 4];  // conflict-free
                unsigned long long e0 = dup_f32(er.x);
                unsigned long long e1 = dup_f32(er.y);
                unsigned long long e2 = dup_f32(er.z);
                unsigned long long e3 = dup_f32(er.w);
                fma_f32x2(acc[0][0], zlo.x, e0); fma_f32x2(acc[0][1], zlo.x, e1);
                fma_f32x2(acc[0][2], zlo.x, e2); fma_f32x2(acc[0][3], zlo.x, e3);
                fma_f32x2(acc[1][0], zlo.y, e0); fma_f32x2(acc[1][1], zlo.y, e1);
                fma_f32x2(acc[1][2], zlo.y, e2); fma_f32x2(acc[1][3], zlo.y, e3);
                fma_f32x2(acc[2][0], zhi.x, e0); fma_f32x2(acc[2][1], zhi.x, e1);
                fma_f32x2(acc[2][2], zhi.x, e2); fma_f32x2(acc[2][3], zhi.x, e3);
                fma_f32x2(acc[3][0], zhi.y, e0); fma_f32x2(acc[3][1], zhi.y, e1);
                fma_f32x2(acc[3][2], zhi.y, e2); fma_f32x2(acc[3][3], zhi.y, e3);
            }
            __syncthreads();   // chunk g consumed; buffer for g+1 ready
        }
        // scores; per-pixel scan order ascending k -> first-min tie-break
#pragma unroll
        for (int j = 0; j < 4; j++) {
            int k = kt * 128 + lane * 4 + j;
            float ee = g_ee[k];
#pragma unroll
            for (int pq = 0; pq < 4; pq++) {
                float dlo, dhi;
                unpack_f32x2(dlo, dhi, acc[pq][j]);
                float d2lo = __fadd_rn(__fsub_rn(zzr[2 * pq + 0], __fmul_rn(2.0f, dlo)), ee);
                float d2hi = __fadd_rn(__fsub_rn(zzr[2 * pq + 1], __fmul_rn(2.0f, dhi)), ee);
                if (d2lo < bestv[2 * pq + 0]) { bestv[2 * pq + 0] = d2lo; besti[2 * pq + 0] = k; }
                if (d2hi < bestv[2 * pq + 1]) { bestv[2 * pq + 1] = d2hi; besti[2 * pq + 1] = k; }
            }
        }
    }
    // warp reduction; tie -> smaller index (jnp.argmin first-occurrence)
#pragma unroll
    for (int off = 16; off > 0; off >>= 1) {
#pragma unroll
        for (int pp = 0; pp < 8; pp++) {
            float ov = __shfl_down_sync(0xffffffffu, bestv[pp], off);
            int   oi = __shfl_down_sync(0xffffffffu, besti[pp], off);
            if (ov < bestv[pp] || (ov == bestv[pp] && oi < besti[pp])) {
                bestv[pp] = ov; besti[pp] = oi;
            }
        }
    }
    if (lane == 0) {
#pragma unroll
        for (int pp = 0; pp < 8; pp++) g_idx[n0 + tp * 8 + pp] = besti[pp];
    }
}

// ------------------------------------------------------------------
// gather + straight-through output + deterministic loss partials.
// ------------------------------------------------------------------
__global__ void __launch_bounds__(256) quant_kernel(
        const float* __restrict__ z, const float* __restrict__ cb,
        float* __restrict__ outq, int total) {
    __shared__ double sh[8];
    double sq = 0.0;
    const int stride = gridDim.x * blockDim.x * 4;
    int total4 = total & ~3;
    for (int base = (blockIdx.x * blockDim.x + threadIdx.x) * 4; base < total4;
         base += stride) {
        float4 zv = *(const float4*)(z + base);
        int hw = base & (HWDIM - 1);            // 4 elems stay in one (b,c) row
        int c  = (base >> 12) & (CDIM - 1);
        int b  = base >> 19;
        int n  = b * HWDIM + hw;
        float q0 = cb[(size_t)g_idx[n + 0] * CDIM + c];
        float q1 = cb[(size_t)g_idx[n + 1] * CDIM + c];
        float q2 = cb[(size_t)g_idx[n + 2] * CDIM + c];
        float q3 = cb[(size_t)g_idx[n + 3] * CDIM + c];
        float4 o;
        o.x = __fadd_rn(zv.x, __fsub_rn(q0, zv.x));   // exact STE rounding
        o.y = __fadd_rn(zv.y, __fsub_rn(q1, zv.y));
        o.z = __fadd_rn(zv.z, __fsub_rn(q2, zv.z));
        o.w = __fadd_rn(zv.w, __fsub_rn(q3, zv.w));
        *(float4*)(outq + base) = o;
        float d0 = __fsub_rn(zv.x, q0), d1 = __fsub_rn(zv.y, q1);
        float d2 = __fsub_rn(zv.z, q2), d3 = __fsub_rn(zv.w, q3);
        sq += (double)__fmul_rn(d0, d0);
        sq += (double)__fmul_rn(d1, d1);
        sq += (double)__fmul_rn(d2, d2);
        sq += (double)__fmul_rn(d3, d3);
    }
    for (int i = total4 + blockIdx.x * blockDim.x + threadIdx.x; i < total;
         i += gridDim.x * blockDim.x) {
        int hw = i & (HWDIM - 1);
        int c  = (i >> 12) & (CDIM - 1);
        int b  = i >> 19;
        int k  = g_idx[b * HWDIM + hw];
        float zv = z[i];
        float q  = cb[(size_t)k * CDIM + c];
        outq[i]  = __fadd_rn(zv, __fsub_rn(q, zv));
        float d  = __fsub_rn(zv, q);
        sq += (double)__fmul_rn(d, d);
    }
#pragma unroll
    for (int off = 16; off > 0; off >>= 1)
        sq += __shfl_down_sync(0xffffffffu, sq, off);
    int warp = threadIdx.x >> 5;
    if ((threadIdx.x & 31) == 0) sh[warp] = sq;
    __syncthreads();
    if (threadIdx.x == 0) {
        double s = 0.0;
        for (int w = 0; w < 8; w++) s += sh[w];   // fixed order -> deterministic
        g_partials[blockIdx.x] = s;
    }
}

// ------------------------------------------------------------------
__global__ void hist_kernel(float* __restrict__ idx_out, int npix, int write_out) {
    __shared__ int h[KCODES];
    float* dst = write_out ? idx_out : g_idx_scratch;
    for (int i = threadIdx.x; i < KCODES; i += blockDim.x) h[i] = 0;
    __syncthreads();
    for (int n = blockIdx.x * blockDim.x + threadIdx.x; n < npix;
         n += gridDim.x * blockDim.x) {
        int k = g_idx[n];
        atomicAdd(&h[k], 1);
        dst[n] = (float)k;
    }
    __syncthreads();
    for (int i = threadIdx.x; i < KCODES; i += blockDim.x)
        if (h[i]) atomicAdd(&g_counts[i], h[i]);
}

// ------------------------------------------------------------------
__global__ void finalize_kernel(float* __restrict__ out2, int nblocks,
                                double inv_total, int npix) {
    __shared__ double sh[256];
    __shared__ double sh2[256];
    double s = 0.0;
    for (int i = threadIdx.x; i < nblocks; i += 256) s += g_partials[i];
    double h = 0.0;
    double inv_n = 1.0 / (double)npix;
    for (int k = threadIdx.x; k < KCODES; k += 256) {
        double p = (double)g_counts[k] * inv_n;
        h -= p * log(p + 1e-10);
    }
    sh[threadIdx.x]  = s;
    sh2[threadIdx.x] = h;
    __syncthreads();
    for (int st = 128; st > 0; st >>= 1) {
        if (threadIdx.x < st) {
            sh[threadIdx.x]  += sh[threadIdx.x + st];
            sh2[threadIdx.x] += sh2[threadIdx.x + st];
        }
        __syncthreads();
    }
    if (threadIdx.x == 0) {
        double mse = sh[0] * inv_total;
        float m  = (float)mse;
        out2[0] = __fadd_rn(m, __fmul_rn(0.25f, m));
        out2[1] = (float)exp(sh2[0]);
    }
}

// ------------------------------------------------------------------
// Output layout (all float32): [quantized (total) | indices (npix) |
// vq_loss (1) | perplexity (1)] — guarded by out_size.
// ------------------------------------------------------------------
extern "C" void kernel_launch(void* const* d_in, const int* in_sizes, int n_in,
                              void* d_out, int out_size) {
    const float* z  = (const float*)d_in[0];
    const float* cb = (const float*)d_in[1];
    float* out = (float*)d_out;

    int total = in_sizes[0];          // 8388608
    int npix  = total / CDIM;         // 65536

    zero_counts_kernel<<<(KCODES + 255) / 256, 256>>>();
    ee_kernel<<<(KCODES + 255) / 256, 256>>>(cb);
    argmin_kernel<<<npix / 64, 256>>>(z, cb);
    quant_kernel<<<PBLOCKS, 256>>>(z, cb, out, total);

    int write_idx = (out_size >= total + npix) ? 1 : 0;
    hist_kernel<<<64, 256>>>(out + total, npix, write_idx);

    if (out_size >= total + npix + 2) {
        finalize_kernel<<<1, 256>>>(out + total + npix, PBLOCKS,
                                    1.0 / (double)total, npix);
    }
    (void)n_in;
}

// round 5
// speedup vs baseline: 1.0543x; 1.0543x over previous
#include <cuda_runtime.h>
#include <math.h>

// Problem constants (fixed shapes: z = (16, 128, 64, 64) fp32, codebook = (1024, 128) fp32)
#define CDIM    128
#define KCODES  1024
#define HWDIM   4096          // 64*64 pixels per batch image
#define NPIXMAX 65536         // 16 * 4096
#define PBLOCKS 1024          // quant partial blocks

// ---- scratch (no allocations allowed; __device__ globals are the sanctioned path) ----
__device__ float  g_ee[KCODES];          // per-code sum(e^2), sequential fp32
__device__ int    g_idx[NPIXMAX];        // argmin indices
__device__ int    g_counts[KCODES];      // code histogram
__device__ double g_partials[PBLOCKS];   // deterministic per-block loss partials
__device__ float  g_idx_scratch[NPIXMAX];// fallback index sink if out buffer too small

// ---- packed fp32x2 helpers (lanewise IEEE fp32 => numerics identical to scalar) ----
__device__ __forceinline__ unsigned long long dup_f32(float x) {
    unsigned long long r;
    asm("mov.b64 %0, {%1, %1};" : "=l"(r) : "f"(x));
    return r;
}
__device__ __forceinline__ void fma_f32x2(unsigned long long& d,
                                          unsigned long long a,
                                          unsigned long long b) {
    asm("fma.rn.f32x2 %0, %1, %2, %3;" : "=l"(d) : "l"(a), "l"(b), "l"(d));
}
__device__ __forceinline__ void unpack_f32x2(float& lo, float& hi, unsigned long long v) {
    asm("mov.b64 {%0, %1}, %2;" : "=f"(lo), "=f"(hi) : "l"(v));
}

// ------------------------------------------------------------------
__global__ void zero_counts_kernel() {
    int i = blockIdx.x * blockDim.x + threadIdx.x;
    if (i < KCODES) g_counts[i] = 0;
}

// ------------------------------------------------------------------
__global__ void ee_kernel(const float* __restrict__ cb) {
    int k = blockIdx.x * blockDim.x + threadIdx.x;
    if (k >= KCODES) return;
    const float* p = cb + (size_t)k * CDIM;
    float s = 0.0f;
#pragma unroll
    for (int c = 0; c < CDIM; c++) {
        float v = p[c];
        s = __fadd_rn(s, __fmul_rn(v, v));
    }
    g_ee[k] = s;
}

// ------------------------------------------------------------------
// argmin: block = 64 pixels x all 1024 codes, 256 threads.
// z tile in smem once. Codebook streamed as 64 chunks (128 codes x
// 16 c), double-buffered with REGISTER staging at distance 2:
//   iter g: STS(regs holding chunk g+1)  -> never stalls on memory
//           LDG(chunk g+2 -> regs)       -> covered by 2 compute windows
//           compute chunk g; ONE __syncthreads
// Inner product = packed fma.rn.f32x2 over pixel pairs; per-lane chain
// is the sequential ascending-c fp32 FMA chain (bit-validated R1-R4).
// d2 = fl(fl(zz - fl(2*dot)) + ee); first-minimum tie-break.
// ------------------------------------------------------------------
__global__ void __launch_bounds__(256, 2) argmin_kernel(
        const float* __restrict__ z, const float* __restrict__ cb) {
    __shared__ __align__(16) float zs[CDIM][64];    // 32KB, c-major (pairs adjacent)
    __shared__ __align__(16) float es[2][16][128];  // 16KB, [buf][c-slice][code]

    const int tid  = threadIdx.x;
    const int lane = tid & 31;
    const int tp   = tid >> 5;

    const int n0  = blockIdx.x * 64;        // 4096 % 64 == 0 -> tile never straddles b
    const int b   = n0 >> 12;
    const int hw0 = n0 & (HWDIM - 1);
    const float* zbase = z + ((size_t)b * CDIM) * HWDIM + hw0;

    // chunk-loader geometry: thread covers code kk, c-halves hb..hb+7 of a 16-c chunk
    const int kk = tid & 127;
    const int hb = (tid >> 7) * 8;
    const float* cbt = cb + (size_t)kk * CDIM + hb;

    // ---- load full z tile (128 rows x 64 floats, float4, coalesced) ----
#pragma unroll
    for (int pass = 0; pass < 8; pass++) {
        int r = (tid >> 4) + pass * 16;
        int q = (tid & 15) * 4;
        *(float4*)&zs[r][q] = *(const float4*)(zbase + (size_t)r * HWDIM + q);
    }
    // ---- stage chunk 0 (kt=0, c 0..15) into registers ----
    float4 st0 = *(const float4*)(cbt + 0);
    float4 st1 = *(const float4*)(cbt + 4);
    __syncthreads();                         // zs visible

    // ---- zz from smem: strictly sequential fp32 (bit-identical, R4-validated)
    //      also covers the chunk-0 LDG latency before the stores below ----
    float zzr[8];
#pragma unroll
    for (int pp = 0; pp < 8; pp++) zzr[pp] = 0.0f;
    for (int c = 0; c < CDIM; c++) {
#pragma unroll
        for (int pp = 0; pp < 8; pp++) {
            float v = zs[c][tp * 8 + pp];
            zzr[pp] = __fadd_rn(zzr[pp], __fmul_rn(v, v));
        }
    }
    // ---- store chunk 0 -> es[0]; stage chunk 1 (kt=0, c 16..31) ----
    es[0][hb + 0][kk] = st0.x; es[0][hb + 1][kk] = st0.y;
    es[0][hb + 2][kk] = st0.z; es[0][hb + 3][kk] = st0.w;
    es[0][hb + 4][kk] = st1.x; es[0][hb + 5][kk] = st1.y;
    es[0][hb + 6][kk] = st1.z; es[0][hb + 7][kk] = st1.w;
    st0 = *(const float4*)(cbt + 16);
    st1 = *(const float4*)(cbt + 20);
    __syncthreads();                         // es[0] visible

    float bestv[8];
    int   besti[8];
#pragma unroll
    for (int pp = 0; pp < 8; pp++) { bestv[pp] = 3.4e38f; besti[pp] = 0x7fffffff; }

#pragma unroll 1
    for (int kt = 0; kt < 8; kt++) {
        // acc[pq][j]: pq = pixel pair (lo = pixel 2pq, hi = 2pq+1), j = code
        unsigned long long acc[4][4];
#pragma unroll
        for (int pq = 0; pq < 4; pq++)
#pragma unroll
            for (int j = 0; j < 4; j++) acc[pq][j] = 0ull;

#pragma unroll 1
        for (int cc = 0; cc < 8; cc++) {
            const int g   = kt * 8 + cc;
            const int buf = g & 1;
            // stores of chunk g+1 (data already in regs -> no memory stall);
            // readers of buffer (g+1)&1 finished at the barrier ending iter g-1
            if (g + 1 < 64) {
                const int nb = (g + 1) & 1;
                es[nb][hb + 0][kk] = st0.x; es[nb][hb + 1][kk] = st0.y;
                es[nb][hb + 2][kk] = st0.z; es[nb][hb + 3][kk] = st0.w;
                es[nb][hb + 4][kk] = st1.x; es[nb][hb + 5][kk] = st1.y;
                es[nb][hb + 6][kk] = st1.z; es[nb][hb + 7][kk] = st1.w;
            }
            // issue LDG for chunk g+2 (consumed 2 iterations later)
            if (g + 2 < 64) {
                const int g2 = g + 2;
                const float* src =
                    cb + (size_t)((g2 >> 3) * 128 + kk) * CDIM + (g2 & 7) * 16 + hb;
                st0 = *(const float4*)(src + 0);
                st1 = *(const float4*)(src + 4);
            }
            // compute the 16 c-slices of chunk g
#pragma unroll
            for (int t = 0; t < 16; t++) {
                const int c = cc * 16 + t;
                ulonglong2 zlo = *(const ulonglong2*)&zs[c][tp * 8];       // broadcast
                ulonglong2 zhi = *(const ulonglong2*)&zs[c][tp * 8 + 4];   // broadcast
                float4 er = *(const float4*)&es[buf][t][lane * 4];         // conflict-free
                unsigned long long e0 = dup_f32(er.x);
                unsigned long long e1 = dup_f32(er.y);
                unsigned long long e2 = dup_f32(er.z);
                unsigned long long e3 = dup_f32(er.w);
                fma_f32x2(acc[0][0], zlo.x, e0); fma_f32x2(acc[0][1], zlo.x, e1);
                fma_f32x2(acc[0][2], zlo.x, e2); fma_f32x2(acc[0][3], zlo.x, e3);
                fma_f32x2(acc[1][0], zlo.y, e0); fma_f32x2(acc[1][1], zlo.y, e1);
                fma_f32x2(acc[1][2], zlo.y, e2); fma_f32x2(acc[1][3], zlo.y, e3);
                fma_f32x2(acc[2][0], zhi.x, e0); fma_f32x2(acc[2][1], zhi.x, e1);
                fma_f32x2(acc[2][2], zhi.x, e2); fma_f32x2(acc[2][3], zhi.x, e3);
                fma_f32x2(acc[3][0], zhi.y, e0); fma_f32x2(acc[3][1], zhi.y, e1);
                fma_f32x2(acc[3][2], zhi.y, e2); fma_f32x2(acc[3][3], zhi.y, e3);
            }
            __syncthreads();   // single barrier per chunk
        }
        // scores; per-pixel scan order ascending k -> first-min tie-break
#pragma unroll
        for (int j = 0; j < 4; j++) {
            int k = kt * 128 + lane * 4 + j;
            float ee = g_ee[k];
#pragma unroll
            for (int pq = 0; pq < 4; pq++) {
                float dlo, dhi;
                unpack_f32x2(dlo, dhi, acc[pq][j]);
                float d2lo = __fadd_rn(__fsub_rn(zzr[2 * pq + 0], __fmul_rn(2.0f, dlo)), ee);
                float d2hi = __fadd_rn(__fsub_rn(zzr[2 * pq + 1], __fmul_rn(2.0f, dhi)), ee);
                if (d2lo < bestv[2 * pq + 0]) { bestv[2 * pq + 0] = d2lo; besti[2 * pq + 0] = k; }
                if (d2hi < bestv[2 * pq + 1]) { bestv[2 * pq + 1] = d2hi; besti[2 * pq + 1] = k; }
            }
        }
    }
    // warp reduction; tie -> smaller index (jnp.argmin first-occurrence)
#pragma unroll
    for (int off = 16; off > 0; off >>= 1) {
#pragma unroll
        for (int pp = 0; pp < 8; pp++) {
            float ov = __shfl_down_sync(0xffffffffu, bestv[pp], off);
            int   oi = __shfl_down_sync(0xffffffffu, besti[pp], off);
            if (ov < bestv[pp] || (ov == bestv[pp] && oi < besti[pp])) {
                bestv[pp] = ov; besti[pp] = oi;
            }
        }
    }
    if (lane == 0) {
#pragma unroll
        for (int pp = 0; pp < 8; pp++) g_idx[n0 + tp * 8 + pp] = besti[pp];
    }
}

// ------------------------------------------------------------------
// gather + straight-through output + deterministic loss partials.
// ------------------------------------------------------------------
__global__ void __launch_bounds__(256) quant_kernel(
        const float* __restrict__ z, const float* __restrict__ cb,
        float* __restrict__ outq, int total) {
    __shared__ double sh[8];
    double sq = 0.0;
    const int stride = gridDim.x * blockDim.x * 4;
    int total4 = total & ~3;
    for (int base = (blockIdx.x * blockDim.x + threadIdx.x) * 4; base < total4;
         base += stride) {
        float4 zv = *(const float4*)(z + base);
        int hw = base & (HWDIM - 1);            // 4 elems stay in one (b,c) row
        int c  = (base >> 12) & (CDIM - 1);
        int b  = base >> 19;
        int n  = b * HWDIM + hw;
        float q0 = cb[(size_t)g_idx[n + 0] * CDIM + c];
        float q1 = cb[(size_t)g_idx[n + 1] * CDIM + c];
        float q2 = cb[(size_t)g_idx[n + 2] * CDIM + c];
        float q3 = cb[(size_t)g_idx[n + 3] * CDIM + c];
        float4 o;
        o.x = __fadd_rn(zv.x, __fsub_rn(q0, zv.x));   // exact STE rounding
        o.y = __fadd_rn(zv.y, __fsub_rn(q1, zv.y));
        o.z = __fadd_rn(zv.z, __fsub_rn(q2, zv.z));
        o.w = __fadd_rn(zv.w, __fsub_rn(q3, zv.w));
        *(float4*)(outq + base) = o;
        float d0 = __fsub_rn(zv.x, q0), d1 = __fsub_rn(zv.y, q1);
        float d2 = __fsub_rn(zv.z, q2), d3 = __fsub_rn(zv.w, q3);
        sq += (double)__fmul_rn(d0, d0);
        sq += (double)__fmul_rn(d1, d1);
        sq += (double)__fmul_rn(d2, d2);
        sq += (double)__fmul_rn(d3, d3);
    }
    for (int i = total4 + blockIdx.x * blockDim.x + threadIdx.x; i < total;
         i += gridDim.x * blockDim.x) {
        int hw = i & (HWDIM - 1);
        int c  = (i >> 12) & (CDIM - 1);
        int b  = i >> 19;
        int k  = g_idx[b * HWDIM + hw];
        float zv = z[i];
        float q  = cb[(size_t)k * CDIM + c];
        outq[i]  = __fadd_rn(zv, __fsub_rn(q, zv));
        float d  = __fsub_rn(zv, q);
        sq += (double)__fmul_rn(d, d);
    }
#pragma unroll
    for (int off = 16; off > 0; off >>= 1)
        sq += __shfl_down_sync(0xffffffffu, sq, off);
    int warp = threadIdx.x >> 5;
    if ((threadIdx.x & 31) == 0) sh[warp] = sq;
    __syncthreads();
    if (threadIdx.x == 0) {
        double s = 0.0;
        for (int w = 0; w < 8; w++) s += sh[w];   // fixed order -> deterministic
        g_partials[blockIdx.x] = s;
    }
}

// ------------------------------------------------------------------
__global__ void hist_kernel(float* __restrict__ idx_out, int npix, int write_out) {
    __shared__ int h[KCODES];
    float* dst = write_out ? idx_out : g_idx_scratch;
    for (int i = threadIdx.x; i < KCODES; i += blockDim.x) h[i] = 0;
    __syncthreads();
    for (int n = blockIdx.x * blockDim.x + threadIdx.x; n < npix;
         n += gridDim.x * blockDim.x) {
        int k = g_idx[n];
        atomicAdd(&h[k], 1);
        dst[n] = (float)k;
    }
    __syncthreads();
    for (int i = threadIdx.x; i < KCODES; i += blockDim.x)
        if (h[i]) atomicAdd(&g_counts[i], h[i]);
}

// ------------------------------------------------------------------
__global__ void finalize_kernel(float* __restrict__ out2, int nblocks,
                                double inv_total, int npix) {
    __shared__ double sh[256];
    __shared__ double sh2[256];
    double s = 0.0;
    for (int i = threadIdx.x; i < nblocks; i += 256) s += g_partials[i];
    double h = 0.0;
    double inv_n = 1.0 / (double)npix;
    for (int k = threadIdx.x; k < KCODES; k += 256) {
        double p = (double)g_counts[k] * inv_n;
        h -= p * log(p + 1e-10);
    }
    sh[threadIdx.x]  = s;
    sh2[threadIdx.x] = h;
    __syncthreads();
    for (int st = 128; st > 0; st >>= 1) {
        if (threadIdx.x < st) {
            sh[threadIdx.x]  += sh[threadIdx.x + st];
            sh2[threadIdx.x] += sh2[threadIdx.x + st];
        }
        __syncthreads();
    }
    if (threadIdx.x == 0) {
        double mse = sh[0] * inv_total;
        float m  = (float)mse;
        out2[0] = __fadd_rn(m, __fmul_rn(0.25f, m));
        out2[1] = (float)exp(sh2[0]);
    }
}

// ------------------------------------------------------------------
// Output layout (all float32): [quantized (total) | indices (npix) |
// vq_loss (1) | perplexity (1)] — guarded by out_size.
// ------------------------------------------------------------------
extern "C" void kernel_launch(void* const* d_in, const int* in_sizes, int n_in,
                              void* d_out, int out_size) {
    const float* z  = (const float*)d_in[0];
    const float* cb = (const float*)d_in[1];
    float* out = (float*)d_out;

    int total = in_sizes[0];          // 8388608
    int npix  = total / CDIM;         // 65536

    zero_counts_kernel<<<(KCODES + 255) / 256, 256>>>();
    ee_kernel<<<(KCODES + 255) / 256, 256>>>(cb);
    argmin_kernel<<<npix / 64, 256>>>(z, cb);
    quant_kernel<<<PBLOCKS, 256>>>(z, cb, out, total);

    int write_idx = (out_size >= total + npix) ? 1 : 0;
    hist_kernel<<<64, 256>>>(out + total, npix, write_idx);

    if (out_size >= total + npix + 2) {
        finalize_kernel<<<1, 256>>>(out + total + npix, PBLOCKS,
                                    1.0 / (double)total, npix);
    }
    (void)n_in;
}

// round 9
// speedup vs baseline: 1.1538x; 1.0944x over previous
#include <cuda_runtime.h>
#include <math.h>

// Problem constants (fixed shapes: z = (16, 128, 64, 64) fp32, codebook = (1024, 128) fp32)
#define CDIM    128
#define KCODES  1024
#define HWDIM   4096          // 64*64 pixels per batch image
#define NPIXMAX 65536         // 16 * 4096
#define PBLOCKS 1024          // quant partial blocks

// ---- scratch (no allocations allowed; __device__ globals are the sanctioned path) ----
__device__ float  g_zz[NPIXMAX];         // per-pixel sum(z^2), sequential fp32
__device__ float  g_ee[KCODES];          // per-code sum(e^2), sequential fp32
__device__ int    g_idx[NPIXMAX];        // argmin indices
__device__ int    g_counts[KCODES];      // code histogram
__device__ double g_partials[PBLOCKS];   // deterministic per-block loss partials
__device__ float  g_idx_scratch[NPIXMAX];// fallback index sink if out buffer too small

// ---- packed fp32x2 helpers (lanewise IEEE fp32 => numerics identical to scalar) ----
__device__ __forceinline__ unsigned long long dup_f32(float x) {
    unsigned long long r;
    asm("mov.b64 %0, {%1, %1};" : "=l"(r) : "f"(x));
    return r;
}
__device__ __forceinline__ void fma_f32x2(unsigned long long& d,
                                          unsigned long long a,
                                          unsigned long long b) {
    asm("fma.rn.f32x2 %0, %1, %2, %3;" : "=l"(d) : "l"(a), "l"(b), "l"(d));
}
__device__ __forceinline__ void unpack_f32x2(float& lo, float& hi, unsigned long long v) {
    asm("mov.b64 {%0, %1}, %2;" : "=f"(lo), "=f"(hi) : "l"(v));
}

// ------------------------------------------------------------------
__global__ void zero_counts_kernel() {
    int i = blockIdx.x * blockDim.x + threadIdx.x;
    if (i < KCODES) g_counts[i] = 0;
}

// ------------------------------------------------------------------
// zz[n] = sum_c fl(z[b,c,hw]^2), strictly sequential fp32 adds
// (separate cheap parallel kernel — in-block variant cost 12.5% of the
// argmin fma budget, identified as part of the R4/R5 regression)
// ------------------------------------------------------------------
__global__ void zz_kernel(const float* __restrict__ z, int npix) {
    int n = blockIdx.x * blockDim.x + threadIdx.x;
    if (n >= npix) return;
    int b  = n / HWDIM;
    int hw = n - b * HWDIM;
    const float* p = z + ((size_t)b * CDIM) * HWDIM + hw;
    float s = 0.0f;
#pragma unroll
    for (int c = 0; c < CDIM; c++) {
        float v = p[(size_t)c * HWDIM];
        s = __fadd_rn(s, __fmul_rn(v, v));   // no FMA, no reassociation
    }
    g_zz[n] = s;
}

// ------------------------------------------------------------------
__global__ void ee_kernel(const float* __restrict__ cb) {
    int k = blockIdx.x * blockDim.x + threadIdx.x;
    if (k >= KCODES) return;
    const float* p = cb + (size_t)k * CDIM;
    float s = 0.0f;
#pragma unroll
    for (int c = 0; c < CDIM; c++) {
        float v = p[c];
        s = __fadd_rn(s, __fmul_rn(v, v));
    }
    g_ee[k] = s;
}

// ------------------------------------------------------------------
// argmin: EXACT R2 skeleton (block = 64 px x 1024 codes, 8-c chunks,
// same load geometry, same fma.rn.f32x2 micro-loop) with two deltas:
//  (1) zs and es are double-buffered -> ONE barrier per chunk (was 2)
//  (2) loads are register-staged at distance 2: iter g stores chunk
//      g+1 from regs (already arrived), issues LDG for chunk g+2.
// Accumulation chains unchanged: per (pixel,code) sequential fp32 FMA
// over ascending c, carried across chunks within each 128-code tile.
// d2 = fl(fl(zz - fl(2*dot)) + ee); first-minimum tie-break.
// ------------------------------------------------------------------
__global__ void __launch_bounds__(256) argmin_kernel(
        const float* __restrict__ z, const float* __restrict__ cb) {
    __shared__ __align__(16) float zs[2][8][64];    // [buf][c][pixel]  4KB
    __shared__ __align__(16) float es[2][8][132];   // [buf][c][code]   8.25KB (padded)

    const int tid  = threadIdx.x;
    const int lane = tid & 31;
    const int tp   = tid >> 5;

    const int n0  = blockIdx.x * 64;        // 4096 % 64 == 0 -> tile never straddles b
    const int b   = n0 >> 12;
    const int hw0 = n0 & (HWDIM - 1);
    const float* zbase = z + ((size_t)b * CDIM) * HWDIM + hw0;

    // load geometry (identical to R2)
    const int zci = tid >> 6;               // 0..3 (rows zci and zci+4)
    const int zp  = tid & 63;
    const int kk  = tid >> 1;               // code 0..127 within tile
    const int h   = (tid & 1) * 4;          // c-half within chunk

    float zzr[8];
#pragma unroll
    for (int pp = 0; pp < 8; pp++) zzr[pp] = g_zz[n0 + tp * 8 + pp];

    float bestv[8];
    int   besti[8];
#pragma unroll
    for (int pp = 0; pp < 8; pp++) { bestv[pp] = 3.4e38f; besti[pp] = 0x7fffffff; }

    // ---- staging registers + prologue: chunk 0 ----
    // chunk g: kt = g>>4 (code tile), c0 = (g&15)*8 (c offset)
    float  zr0, zr1;
    float4 cbv;
    zr0 = zbase[(size_t)(0 + zci) * HWDIM + zp];
    zr1 = zbase[(size_t)(4 + zci) * HWDIM + zp];
    cbv = *(const float4*)(cb + (size_t)kk * CDIM + h);
    // store chunk 0 -> buffer 0 (one-time exposed latency)
    zs[0][zci][zp]     = zr0;
    zs[0][4 + zci][zp] = zr1;
    es[0][h + 0][kk] = cbv.x; es[0][h + 1][kk] = cbv.y;
    es[0][h + 2][kk] = cbv.z; es[0][h + 3][kk] = cbv.w;
    // stage chunk 1
    zr0 = zbase[(size_t)(8 + zci) * HWDIM + zp];
    zr1 = zbase[(size_t)(12 + zci) * HWDIM + zp];
    cbv = *(const float4*)(cb + (size_t)kk * CDIM + 8 + h);
    __syncthreads();                        // buffer 0 visible

    unsigned long long acc[4][4];           // [pixel pair][code j]
#pragma unroll
    for (int pq = 0; pq < 4; pq++)
#pragma unroll
        for (int j = 0; j < 4; j++) acc[pq][j] = 0ull;

#pragma unroll 1
    for (int g = 0; g < 128; g++) {
        const int buf = g & 1;
        // (1) store chunk g+1 from staged regs (data already arrived).
        //     Writers of buf^1 are safe: its readers (chunk g-1) all
        //     passed the barrier ending iter g-1.
        if (g + 1 < 128) {
            const int nb = 1 - buf;
            zs[nb][zci][zp]     = zr0;
            zs[nb][4 + zci][zp] = zr1;
            es[nb][h + 0][kk] = cbv.x; es[nb][h + 1][kk] = cbv.y;
            es[nb][h + 2][kk] = cbv.z; es[nb][h + 3][kk] = cbv.w;
        }
        // (2) issue LDG for chunk g+2 (covered by this iteration's compute)
        if (g + 2 < 128) {
            const int g2  = g + 2;
            const int c02 = (g2 & 15) * 8;
            const int kt2 = g2 >> 4;
            zr0 = zbase[(size_t)(c02 + zci) * HWDIM + zp];
            zr1 = zbase[(size_t)(c02 + 4 + zci) * HWDIM + zp];
            cbv = *(const float4*)(cb + (size_t)(kt2 * 128 + kk) * CDIM + c02 + h);
        }
        // (3) compute chunk g (identical micro-loop to R2)
#pragma unroll
        for (int ci = 0; ci < 8; ci++) {
            ulonglong2 zlo = *(const ulonglong2*)&zs[buf][ci][tp * 8];      // broadcast
            ulonglong2 zhi = *(const ulonglong2*)&zs[buf][ci][tp * 8 + 4];  // broadcast
            float4 er = *(const float4*)&es[buf][ci][lane * 4];             // conflict-free
            unsigned long long e0 = dup_f32(er.x);
            unsigned long long e1 = dup_f32(er.y);
            unsigned long long e2 = dup_f32(er.z);
            unsigned long long e3 = dup_f32(er.w);
            fma_f32x2(acc[0][0], zlo.x, e0); fma_f32x2(acc[0][1], zlo.x, e1);
            fma_f32x2(acc[0][2], zlo.x, e2); fma_f32x2(acc[0][3], zlo.x, e3);
            fma_f32x2(acc[1][0], zlo.y, e0); fma_f32x2(acc[1][1], zlo.y, e1);
            fma_f32x2(acc[1][2], zlo.y, e2); fma_f32x2(acc[1][3], zlo.y, e3);
            fma_f32x2(acc[2][0], zhi.x, e0); fma_f32x2(acc[2][1], zhi.x, e1);
            fma_f32x2(acc[2][2], zhi.x, e2); fma_f32x2(acc[2][3], zhi.x, e3);
            fma_f32x2(acc[3][0], zhi.y, e0); fma_f32x2(acc[3][1], zhi.y, e1);
            fma_f32x2(acc[3][2], zhi.y, e2); fma_f32x2(acc[3][3], zhi.y, e3);
        }
        // (4) end of a 128-code tile? score + reset accumulators
        if ((g & 15) == 15) {
            const int kt = g >> 4;
#pragma unroll
            for (int j = 0; j < 4; j++) {
                int k = kt * 128 + lane * 4 + j;
                float ee = g_ee[k];
#pragma unroll
                for (int pq = 0; pq < 4; pq++) {
                    float dlo, dhi;
                    unpack_f32x2(dlo, dhi, acc[pq][j]);
                    float d2lo = __fadd_rn(__fsub_rn(zzr[2 * pq + 0], __fmul_rn(2.0f, dlo)), ee);
                    float d2hi = __fadd_rn(__fsub_rn(zzr[2 * pq + 1], __fmul_rn(2.0f, dhi)), ee);
                    if (d2lo < bestv[2 * pq + 0]) { bestv[2 * pq + 0] = d2lo; besti[2 * pq + 0] = k; }
                    if (d2hi < bestv[2 * pq + 1]) { bestv[2 * pq + 1] = d2hi; besti[2 * pq + 1] = k; }
                    acc[pq][j] = 0ull;
                }
            }
        }
        __syncthreads();   // single barrier per chunk
    }

    // warp reduction; tie -> smaller index (jnp.argmin first-occurrence)
#pragma unroll
    for (int off = 16; off > 0; off >>= 1) {
#pragma unroll
        for (int pp = 0; pp < 8; pp++) {
            float ov = __shfl_down_sync(0xffffffffu, bestv[pp], off);
            int   oi = __shfl_down_sync(0xffffffffu, besti[pp], off);
            if (ov < bestv[pp] || (ov == bestv[pp] && oi < besti[pp])) {
                bestv[pp] = ov; besti[pp] = oi;
            }
        }
    }
    if (lane == 0) {
#pragma unroll
        for (int pp = 0; pp < 8; pp++) g_idx[n0 + tp * 8 + pp] = besti[pp];
    }
}

// ------------------------------------------------------------------
// gather + straight-through output + deterministic loss partials.
// ------------------------------------------------------------------
__global__ void __launch_bounds__(256) quant_kernel(
        const float* __restrict__ z, const float* __restrict__ cb,
        float* __restrict__ outq, int total) {
    __shared__ double sh[8];
    double sq = 0.0;
    const int stride = gridDim.x * blockDim.x * 4;
    int total4 = total & ~3;
    for (int base = (blockIdx.x * blockDim.x + threadIdx.x) * 4; base < total4;
         base += stride) {
        float4 zv = *(const float4*)(z + base);
        int hw = base & (HWDIM - 1);            // 4 elems stay in one (b,c) row
        int c  = (base >> 12) & (CDIM - 1);
        int b  = base >> 19;
        int n  = b * HWDIM + hw;
        float q0 = cb[(size_t)g_idx[n + 0] * CDIM + c];
        float q1 = cb[(size_t)g_idx[n + 1] * CDIM + c];
        float q2 = cb[(size_t)g_idx[n + 2] * CDIM + c];
        float q3 = cb[(size_t)g_idx[n + 3] * CDIM + c];
        float4 o;
        o.x = __fadd_rn(zv.x, __fsub_rn(q0, zv.x));   // exact STE rounding
        o.y = __fadd_rn(zv.y, __fsub_rn(q1, zv.y));
        o.z = __fadd_rn(zv.z, __fsub_rn(q2, zv.z));
        o.w = __fadd_rn(zv.w, __fsub_rn(q3, zv.w));
        *(float4*)(outq + base) = o;
        float d0 = __fsub_rn(zv.x, q0), d1 = __fsub_rn(zv.y, q1);
        float d2 = __fsub_rn(zv.z, q2), d3 = __fsub_rn(zv.w, q3);
        sq += (double)__fmul_rn(d0, d0);
        sq += (double)__fmul_rn(d1, d1);
        sq += (double)__fmul_rn(d2, d2);
        sq += (double)__fmul_rn(d3, d3);
    }
    for (int i = total4 + blockIdx.x * blockDim.x + threadIdx.x; i < total;
         i += gridDim.x * blockDim.x) {
        int hw = i & (HWDIM - 1);
        int c  = (i >> 12) & (CDIM - 1);
        int b  = i >> 19;
        int k  = g_idx[b * HWDIM + hw];
        float zv = z[i];
        float q  = cb[(size_t)k * CDIM + c];
        outq[i]  = __fadd_rn(zv, __fsub_rn(q, zv));
        float d  = __fsub_rn(zv, q);
        sq += (double)__fmul_rn(d, d);
    }
#pragma unroll
    for (int off = 16; off > 0; off >>= 1)
        sq += __shfl_down_sync(0xffffffffu, sq, off);
    int warp = threadIdx.x >> 5;
    if ((threadIdx.x & 31) == 0) sh[warp] = sq;
    __syncthreads();
    if (threadIdx.x == 0) {
        double s = 0.0;
        for (int w = 0; w < 8; w++) s += sh[w];   // fixed order -> deterministic
        g_partials[blockIdx.x] = s;
    }
}

// ------------------------------------------------------------------
__global__ void hist_kernel(float* __restrict__ idx_out, int npix, int write_out) {
    __shared__ int h[KCODES];
    float* dst = write_out ? idx_out : g_idx_scratch;
    for (int i = threadIdx.x; i < KCODES; i += blockDim.x) h[i] = 0;
    __syncthreads();
    for (int n = blockIdx.x * blockDim.x + threadIdx.x; n < npix;
         n += gridDim.x * blockDim.x) {
        int k = g_idx[n];
        atomicAdd(&h[k], 1);
        dst[n] = (float)k;
    }
    __syncthreads();
    for (int i = threadIdx.x; i < KCODES; i += blockDim.x)
        if (h[i]) atomicAdd(&g_counts[i], h[i]);
}

// ------------------------------------------------------------------
__global__ void finalize_kernel(float* __restrict__ out2, int nblocks,
                                double inv_total, int npix) {
    __shared__ double sh[256];
    __shared__ double sh2[256];
    double s = 0.0;
    for (int i = threadIdx.x; i < nblocks; i += 256) s += g_partials[i];
    double h = 0.0;
    double inv_n = 1.0 / (double)npix;
    for (int k = threadIdx.x; k < KCODES; k += 256) {
        double p = (double)g_counts[k] * inv_n;
        h -= p * log(p + 1e-10);
    }
    sh[threadIdx.x]  = s;
    sh2[threadIdx.x] = h;
    __syncthreads();
    for (int st = 128; st > 0; st >>= 1) {
        if (threadIdx.x < st) {
            sh[threadIdx.x]  += sh[threadIdx.x + st];
            sh2[threadIdx.x] += sh2[threadIdx.x + st];
        }
        __syncthreads();
    }
    if (threadIdx.x == 0) {
        double mse = sh[0] * inv_total;
        float m  = (float)mse;
        out2[0] = __fadd_rn(m, __fmul_rn(0.25f, m));
        out2[1] = (float)exp(sh2[0]);
    }
}

// ------------------------------------------------------------------
// Output layout (all float32): [quantized (total) | indices (npix) |
// vq_loss (1) | perplexity (1)] — guarded by out_size.
// ------------------------------------------------------------------
extern "C" void kernel_launch(void* const* d_in, const int* in_sizes, int n_in,
                              void* d_out, int out_size) {
    const float* z  = (const float*)d_in[0];
    const float* cb = (const float*)d_in[1];
    float* out = (float*)d_out;

    int total = in_sizes[0];          // 8388608
    int npix  = total / CDIM;         // 65536

    zero_counts_kernel<<<(KCODES + 255) / 256, 256>>>();
    zz_kernel<<<(npix + 255) / 256, 256>>>(z, npix);
    ee_kernel<<<(KCODES + 255) / 256, 256>>>(cb);
    argmin_kernel<<<npix / 64, 256>>>(z, cb);
    quant_kernel<<<PBLOCKS, 256>>>(z, cb, out, total);

    int write_idx = (out_size >= total + npix) ? 1 : 0;
    hist_kernel<<<64, 256>>>(out + total, npix, write_idx);

    if (out_size >= total + npix + 2) {
        finalize_kernel<<<1, 256>>>(out + total + npix, PBLOCKS,
                                    1.0 / (double)total, npix);
    }
    (void)n_in;
}